// round 15
// baseline (speedup 1.0000x reference)
#include <cuda_runtime.h>
#include <cuda_pipeline.h>
#include <mma.h>
#include <math.h>
#include <stdint.h>

using namespace nvcuda;

// ---------------- problem constants ----------------
#define NL       2
#define DMODEL   512
#define ED       1024
#define DSTATE   16
#define DCONV    4
#define DTRANK   32
#define INPUT_D  64
#define BSZ      2
#define LSEQ     2048
#define T        (BSZ*LSEQ)          // 4096 tokens

// chunked scan
#define NC       16
#define CL       (LSEQ/NC)           // 128
#define NCHAN    (BSZ*ED)            // 2048

// ---------------- scratch (single device global, no allocs) ----------------
#define OFF_H     0
#define OFF_HN    (OFF_H  + T*DMODEL)
#define OFF_XZ    (OFF_HN + T*DMODEL)
#define OFF_XI    (OFF_XZ + T*2*ED)
#define OFF_DELTA (OFF_XI + T*ED)
#define OFF_Y     (OFF_DELTA + T*ED)
#define OFF_DBC   (OFF_Y  + T*ED)
#define OFF_P     (OFF_DBC + T*64)
#define OFF_Q     (OFF_P + NCHAN*NC*DSTATE)
#define OFF_S0    (OFF_Q + NCHAN*NC*DSTATE)
#define OFF_DBCP  (OFF_S0 + NCHAN*NC*DSTATE)
#define SCRATCH_FLOATS (OFF_DBCP + 4*T*64)

__device__ float g_scratch[SCRATCH_FLOATS];

// ---------------- helpers ----------------
__device__ __forceinline__ float softplus_f(float x) {
    return x > 20.f ? x : log1pf(__expf(x));
}
__device__ __forceinline__ float silu_f(float x) {
    return x / (1.f + __expf(-x));
}

// ---------------- TF32 tensor-core GEMM: C[M,N] = A[M,K] @ W[N,K]^T ---------
// 4-stage cp.async pipeline, one __syncthreads per K-block, fused epilogues.
// Split-K via gridDim.z (A/W offset z*K, C offset z*c_zstride).
#define STAGES 4

template<int BM, int BN, int BK, int TPB, bool BIAS, bool SOFTPLUS, bool RES>
__global__ __launch_bounds__(TPB)
void gemm_tf32(const float* __restrict__ A, int lda,
               const float* __restrict__ W, int ldw,
               const float* __restrict__ bias,
               const float* __restrict__ res,
               float* __restrict__ C, int N, int K, size_t c_zstride)
{
    constexpr int NWARP   = TPB / 32;
    constexpr int WARPS_M = BM / 32;
    constexpr int WARPS_N = NWARP / WARPS_M;
    constexpr int WN      = BN / WARPS_N;
    constexpr int MI      = 2;
    constexpr int NI      = WN / 16;
    constexpr int LDS     = BK + 4;

    extern __shared__ float sm[];
    float* As = sm;                          // [STAGES][BM][LDS]
    float* Ws = sm + (size_t)STAGES * BM * LDS;

    const int tid = threadIdx.x;
    const int m0 = blockIdx.y * BM;
    const int n0 = blockIdx.x * BN;
    const int z  = blockIdx.z;
    A += (size_t)z * K;
    W += (size_t)z * K;
    C += (size_t)z * c_zstride;

    const int wid = tid >> 5;
    const int wm = (wid % WARPS_M) * 32;
    const int wn = (wid / WARPS_M) * WN;

    wmma::fragment<wmma::accumulator, 16, 16, 8, float> acc[MI][NI];
#pragma unroll
    for (int mi = 0; mi < MI; mi++)
#pragma unroll
        for (int ni = 0; ni < NI; ni++)
            wmma::fill_fragment(acc[mi][ni], 0.0f);

    constexpr int F4R  = BK / 4;
    constexpr int A_F4 = BM * F4R;
    constexpr int TOT  = A_F4 + BN * F4R;
    constexpr int ITER = TOT / TPB;

    auto load_stage = [&](int s, int k0) {
#pragma unroll
        for (int i = 0; i < ITER; i++) {
            int lin = tid + i * TPB;
            if (lin < A_F4) {
                int row = lin / F4R, c = (lin % F4R) * 4;
                __pipeline_memcpy_async(
                    &As[(size_t)(s * BM + row) * LDS + c],
                    &A[(size_t)(m0 + row) * lda + k0 + c], 16);
            } else {
                int l2 = lin - A_F4;
                int row = l2 / F4R, c = (l2 % F4R) * 4;
                __pipeline_memcpy_async(
                    &Ws[(size_t)(s * BN + row) * LDS + c],
                    &W[(size_t)(n0 + row) * ldw + k0 + c], 16);
            }
        }
        __pipeline_commit();
    };

    const int nk = K / BK;

    // prologue: fill STAGES-1 stages (dummy commits keep group accounting uniform)
#pragma unroll
    for (int s = 0; s < STAGES - 1; s++) {
        if (s < nk) load_stage(s, s * BK);
        else        __pipeline_commit();
    }

    for (int kb = 0; kb < nk; kb++) {
        __pipeline_wait_prior(STAGES - 2);   // stage kb resident
        __syncthreads();                     // all warps done with stage kb-1

        const int kn = kb + STAGES - 1;      // refill the buffer freed last iter
        if (kn < nk) load_stage(kn % STAGES, kn * BK);
        else         __pipeline_commit();

        const int st = kb % STAGES;
#pragma unroll
        for (int ks = 0; ks < BK / 8; ks++) {
            const int kk = ks * 8;
            wmma::fragment<wmma::matrix_a, 16, 16, 8,
                           wmma::precision::tf32, wmma::row_major> a_frag[MI];
            wmma::fragment<wmma::matrix_b, 16, 16, 8,
                           wmma::precision::tf32, wmma::col_major> b_frag[NI];
#pragma unroll
            for (int mi = 0; mi < MI; mi++) {
                wmma::load_matrix_sync(a_frag[mi],
                    &As[(size_t)(st * BM + wm + mi * 16) * LDS + kk], LDS);
#pragma unroll
                for (int t = 0; t < a_frag[mi].num_elements; t++)
                    a_frag[mi].x[t] = wmma::__float_to_tf32(a_frag[mi].x[t]);
            }
#pragma unroll
            for (int ni = 0; ni < NI; ni++) {
                wmma::load_matrix_sync(b_frag[ni],
                    &Ws[(size_t)(st * BN + wn + ni * 16) * LDS + kk], LDS);
#pragma unroll
                for (int t = 0; t < b_frag[ni].num_elements; t++)
                    b_frag[ni].x[t] = wmma::__float_to_tf32(b_frag[ni].x[t]);
            }
#pragma unroll
            for (int mi = 0; mi < MI; mi++)
#pragma unroll
                for (int ni = 0; ni < NI; ni++)
                    wmma::mma_sync(acc[mi][ni], a_frag[mi], b_frag[ni], acc[mi][ni]);
        }
    }

    if constexpr (BIAS || SOFTPLUS || RES) {
        __syncthreads();                      // before reusing sm as staging
        float* stg = sm + (size_t)wid * (32 * WN);
#pragma unroll
        for (int mi = 0; mi < MI; mi++)
#pragma unroll
            for (int ni = 0; ni < NI; ni++)
                wmma::store_matrix_sync(&stg[(mi * 16) * WN + ni * 16],
                                        acc[mi][ni], WN, wmma::mem_row_major);
        __syncwarp();
        const int lane = tid & 31;
        const size_t m = m0 + wm + lane;
#pragma unroll
        for (int c = 0; c < WN; c += 4) {
            float4 v = *reinterpret_cast<float4*>(&stg[lane * WN + c]);
            const int n = n0 + wn + c;
            if (BIAS) {
                v.x += bias[n];     v.y += bias[n + 1];
                v.z += bias[n + 2]; v.w += bias[n + 3];
            }
            if (SOFTPLUS) {
                v.x = softplus_f(v.x); v.y = softplus_f(v.y);
                v.z = softplus_f(v.z); v.w = softplus_f(v.w);
            }
            if (RES) {
                float4 r = *reinterpret_cast<const float4*>(&res[m * N + n]);
                v.x += r.x; v.y += r.y; v.z += r.z; v.w += r.w;
            }
            *reinterpret_cast<float4*>(&C[m * N + n]) = v;
        }
    } else {
#pragma unroll
        for (int mi = 0; mi < MI; mi++)
#pragma unroll
            for (int ni = 0; ni < NI; ni++)
                wmma::store_matrix_sync(
                    &C[(size_t)(m0 + wm + mi * 16) * N + n0 + wn + ni * 16],
                    acc[mi][ni], N, wmma::mem_row_major);
    }
}

// ---------------- split-K reduction for x_proj -------------------------------
__global__ __launch_bounds__(256)
void reduce4_k(const float* __restrict__ p, float* __restrict__ dbc)
{
    const int i = blockIdx.x * 256 + threadIdx.x;
    dbc[i] = (p[i] + p[i + T*64]) + (p[i + 2*T*64] + p[i + 3*T*64]);
}

// ---------------- rmsnorm over DMODEL=512, one block per token --------------
__global__ __launch_bounds__(256)
void rmsnorm_k(const float* __restrict__ h, const float* __restrict__ w,
               float* __restrict__ out)
{
    const int t = blockIdx.x;
    const float* row = h + (size_t)t * DMODEL;
    const int tid = threadIdx.x;
    float v0 = row[tid], v1 = row[tid + 256];
    float ss = v0 * v0 + v1 * v1;
#pragma unroll
    for (int o = 16; o; o >>= 1) ss += __shfl_xor_sync(0xffffffffu, ss, o);
    __shared__ float red[8];
    if ((tid & 31) == 0) red[tid >> 5] = ss;
    __syncthreads();
    float tot = red[0] + red[1] + red[2] + red[3] +
                red[4] + red[5] + red[6] + red[7];
    float scale = rsqrtf(tot * (1.f / DMODEL) + 1e-5f);
    out[(size_t)t * DMODEL + tid]       = v0 * scale * w[tid];
    out[(size_t)t * DMODEL + tid + 256] = v1 * scale * w[tid + 256];
}

// ---------------- depthwise causal conv (k=4) + bias + silu -----------------
// float4 over e. conv_w layout is (ED, DCONV) with DCONV=4, so each channel's
// 4 taps are ONE contiguous float4: cw4[channel] = (tap0, tap1, tap2, tap3).
__global__ __launch_bounds__(256)
void conv_silu_k(const float* __restrict__ xz, const float* __restrict__ cw,
                 const float* __restrict__ cb, float* __restrict__ xi)
{
    const int gid = blockIdx.x * 256 + threadIdx.x;   // (t*ED + e)/4
    const int e = (gid << 2) & (ED - 1);
    const int t = gid >> 8;
    const int l = t & (LSEQ - 1);
    const float* base = xz + (size_t)t * (2 * ED) + e;
    const float4* cw4 = reinterpret_cast<const float4*>(cw);

    const float4 wc0 = cw4[e + 0];   // taps (k0,k1,k2,k3) for channel e+0
    const float4 wc1 = cw4[e + 1];
    const float4 wc2 = cw4[e + 2];
    const float4 wc3 = cw4[e + 3];

    float4 acc = *reinterpret_cast<const float4*>(&cb[e]);
    float4 v;
    if (l >= 3) {                                     // time l-3 -> tap 0
        v = *reinterpret_cast<const float4*>(base - 3 * 2 * ED);
        acc.x = fmaf(v.x, wc0.x, acc.x); acc.y = fmaf(v.y, wc1.x, acc.y);
        acc.z = fmaf(v.z, wc2.x, acc.z); acc.w = fmaf(v.w, wc3.x, acc.w);
    }
    if (l >= 2) {                                     // time l-2 -> tap 1
        v = *reinterpret_cast<const float4*>(base - 2 * 2 * ED);
        acc.x = fmaf(v.x, wc0.y, acc.x); acc.y = fmaf(v.y, wc1.y, acc.y);
        acc.z = fmaf(v.z, wc2.y, acc.z); acc.w = fmaf(v.w, wc3.y, acc.w);
    }
    if (l >= 1) {                                     // time l-1 -> tap 2
        v = *reinterpret_cast<const float4*>(base - 1 * 2 * ED);
        acc.x = fmaf(v.x, wc0.z, acc.x); acc.y = fmaf(v.y, wc1.z, acc.y);
        acc.z = fmaf(v.z, wc2.z, acc.z); acc.w = fmaf(v.w, wc3.z, acc.w);
    }
    v = *reinterpret_cast<const float4*>(base);       // time l -> tap 3
    acc.x = fmaf(v.x, wc0.w, acc.x); acc.y = fmaf(v.y, wc1.w, acc.y);
    acc.z = fmaf(v.z, wc2.w, acc.z); acc.w = fmaf(v.w, wc3.w, acc.w);

    float4 o = make_float4(silu_f(acc.x), silu_f(acc.y),
                           silu_f(acc.z), silu_f(acc.w));
    *reinterpret_cast<float4*>(&xi[(size_t)t * ED + e]) = o;
}

// ---------------- chunked selective scan -------------------------------------
__global__ __launch_bounds__(256)
void scan_p1(const float* __restrict__ delta, const float* __restrict__ xi,
             const float* __restrict__ dbc, const float* __restrict__ A_log,
             float* __restrict__ Pa, float* __restrict__ Qa)
{
    const int tid = threadIdx.x;
    const int j   = blockIdx.x >> 7;
    const int cb  = blockIdx.x & 127;
    const int cl  = tid >> 4;
    const int n   = tid & 15;
    const int c   = cb * 16 + cl;
    const int b   = c >> 10;
    const int e   = c & (ED - 1);

    const float a = -__expf(A_log[e * DSTATE + n]);
    const size_t t0 = (size_t)b * LSEQ + (size_t)j * CL;
    const float* dp = delta + t0 * ED + e;
    const float* xp = xi    + t0 * ED + e;
    const float* bp = dbc   + t0 * 64 + DTRANK + n;

    float P = 1.f, q = 0.f;
#pragma unroll 4
    for (int l = 0; l < CL; l++) {
        float dv = dp[(size_t)l * ED];
        float xv = xp[(size_t)l * ED];
        float Bv = bp[(size_t)l * 64];
        float dA = __expf(dv * a);
        P *= dA;
        q = fmaf(dA, q, dv * xv * Bv);
    }
    const int o = (c * NC + j) * DSTATE + n;
    Pa[o] = P;
    Qa[o] = q;
}

__global__ __launch_bounds__(256)
void scan_p2(const float* __restrict__ Pa, const float* __restrict__ Qa,
             float* __restrict__ S0)
{
    const int gid = blockIdx.x * 256 + threadIdx.x;
    const int c = gid >> 4;
    const int n = gid & 15;
    const int base = c * NC * DSTATE + n;
    float s = 0.f;
#pragma unroll
    for (int jj = 0; jj < NC; jj++) {
        S0[base + jj * DSTATE] = s;
        s = fmaf(Pa[base + jj * DSTATE], s, Qa[base + jj * DSTATE]);
    }
}

__global__ __launch_bounds__(256)
void scan_p3(const float* __restrict__ delta, const float* __restrict__ xi,
             const float* __restrict__ xz, const float* __restrict__ dbc,
             const float* __restrict__ A_log, const float* __restrict__ Dp,
             const float* __restrict__ S0, float* __restrict__ y)
{
    const int tid = threadIdx.x;
    const int j   = blockIdx.x >> 7;
    const int cb  = blockIdx.x & 127;
    const int cl  = tid >> 4;
    const int n   = tid & 15;
    const int c   = cb * 16 + cl;
    const int b   = c >> 10;
    const int e   = c & (ED - 1);

    const float a  = -__expf(A_log[e * DSTATE + n]);
    const float dE = Dp[e];
    const size_t t0 = (size_t)b * LSEQ + (size_t)j * CL;
    const float* dp = delta + t0 * ED + e;
    const float* xp = xi    + t0 * ED + e;
    const float* zp = xz    + t0 * (2 * ED) + ED + e;
    const float* bp = dbc   + t0 * 64 + DTRANK + n;
    const float* cp = dbc   + t0 * 64 + DTRANK + DSTATE + n;
    float*       yp = y     + t0 * ED + e;

    float s = S0[(c * NC + j) * DSTATE + n];
#pragma unroll 4
    for (int l = 0; l < CL; l++) {
        float dv = dp[(size_t)l * ED];
        float xv = xp[(size_t)l * ED];
        float Bv = bp[(size_t)l * 64];
        float Cv = cp[(size_t)l * 64];
        float dA = __expf(dv * a);
        s = fmaf(dA, s, dv * xv * Bv);
        float p = s * Cv;
        p += __shfl_xor_sync(0xffffffffu, p, 8, 16);
        p += __shfl_xor_sync(0xffffffffu, p, 4, 16);
        p += __shfl_xor_sync(0xffffffffu, p, 2, 16);
        p += __shfl_xor_sync(0xffffffffu, p, 1, 16);
        if (n == 0) {
            float zv = zp[(size_t)l * (2 * ED)];
            yp[(size_t)l * ED] = (p + dE * xv) * silu_f(zv);
        }
    }
}

// ---------------- launcher ----------------------------------------------------
#define SMB(BM,BN,BK) (STAGES*((BM)+(BN))*((BK)+4)*4)

extern "C" void kernel_launch(void* const* d_in, const int* in_sizes, int n_in,
                              void* d_out, int out_size)
{
    (void)in_sizes; (void)n_in; (void)out_size;
    const float* x      = (const float*)d_in[0];
    const float* emb_w  = (const float*)d_in[1];
    const float* emb_b  = (const float*)d_in[2];
    const float* in_w   = (const float*)d_in[3];
    const float* conv_w = (const float*)d_in[4];
    const float* conv_b = (const float*)d_in[5];
    const float* xp_w   = (const float*)d_in[6];
    const float* dt_w   = (const float*)d_in[7];
    const float* dt_b   = (const float*)d_in[8];
    const float* A_log  = (const float*)d_in[9];
    const float* Dparam = (const float*)d_in[10];
    const float* out_w  = (const float*)d_in[11];
    const float* norm_w = (const float*)d_in[12];
    float* out = (float*)d_out;

    float* scratch = nullptr;
    cudaGetSymbolAddress((void**)&scratch, g_scratch);
    float* h     = scratch + OFF_H;
    float* hn    = scratch + OFF_HN;
    float* xz    = scratch + OFF_XZ;
    float* xi    = scratch + OFF_XI;
    float* delta = scratch + OFF_DELTA;
    float* y     = scratch + OFF_Y;
    float* dbc   = scratch + OFF_DBC;
    float* Pa    = scratch + OFF_P;
    float* Qa    = scratch + OFF_Q;
    float* S0    = scratch + OFF_S0;
    float* dbcp  = scratch + OFF_DBCP;

    cudaFuncSetAttribute(gemm_tf32<128,128,32,512,true,false,false>,
        cudaFuncAttributeMaxDynamicSharedMemorySize, SMB(128,128,32));
    cudaFuncSetAttribute(gemm_tf32<128,128,32,512,false,false,false>,
        cudaFuncAttributeMaxDynamicSharedMemorySize, SMB(128,128,32));
    cudaFuncSetAttribute(gemm_tf32<64,64,64,256,false,false,false>,
        cudaFuncAttributeMaxDynamicSharedMemorySize, SMB(64,64,64));
    cudaFuncSetAttribute(gemm_tf32<128,128,32,512,true,true,false>,
        cudaFuncAttributeMaxDynamicSharedMemorySize, SMB(128,128,32));
    cudaFuncSetAttribute(gemm_tf32<128,128,32,512,false,false,true>,
        cudaFuncAttributeMaxDynamicSharedMemorySize, SMB(128,128,32));

    // h = x @ emb_w^T + emb_b          (M=4096, N=512, K=64)
    gemm_tf32<128,128,32,512,true,false,false>
        <<<dim3(DMODEL/128, T/128), 512, SMB(128,128,32)>>>(
        x, INPUT_D, emb_w, INPUT_D, emb_b, nullptr, h, DMODEL, INPUT_D, 0);

    for (int i = 0; i < NL; i++) {
        const float* in_w_i   = in_w   + (size_t)i * 2 * ED * DMODEL;
        const float* conv_w_i = conv_w + (size_t)i * ED * DCONV;
        const float* conv_b_i = conv_b + (size_t)i * ED;
        const float* xp_w_i   = xp_w   + (size_t)i * 64 * ED;
        const float* dt_w_i   = dt_w   + (size_t)i * ED * DTRANK;
        const float* dt_b_i   = dt_b   + (size_t)i * ED;
        const float* A_log_i  = A_log  + (size_t)i * ED * DSTATE;
        const float* D_i      = Dparam + (size_t)i * ED;
        const float* out_w_i  = out_w  + (size_t)i * DMODEL * ED;
        const float* norm_w_i = norm_w + (size_t)i * DMODEL;

        // hn = rmsnorm(h)
        rmsnorm_k<<<T, 256>>>(h, norm_w_i, hn);

        // xz = hn @ in_proj_w^T          (M=4096, N=2048, K=512)
        gemm_tf32<128,128,32,512,false,false,false>
            <<<dim3((2*ED)/128, T/128), 512, SMB(128,128,32)>>>(
            hn, DMODEL, in_w_i, DMODEL, nullptr, nullptr, xz, 2*ED, DMODEL, 0);

        // xi = silu(conv(xz[:, :ED]) + cb)
        conv_silu_k<<<(T*ED)/1024, 256>>>(xz, conv_w_i, conv_b_i, xi);

        // dbc = xi @ x_proj_w^T          (M=4096, N=64, K=1024), split-K=4
        gemm_tf32<64,64,64,256,false,false,false>
            <<<dim3(1, T/64, 4), 256, SMB(64,64,64)>>>(
            xi, ED, xp_w_i, ED, nullptr, nullptr, dbcp, 64, ED/4,
            (size_t)T * 64);
        reduce4_k<<<(T*64)/256, 256>>>(dbcp, dbc);

        // delta = softplus(dbc[:, :32] @ dt_w^T + dt_b)  (M=4096, N=1024, K=32)
        gemm_tf32<128,128,32,512,true,true,false>
            <<<dim3(ED/128, T/128), 512, SMB(128,128,32)>>>(
            dbc, 64, dt_w_i, DTRANK, dt_b_i, nullptr, delta, ED, DTRANK, 0);

        // chunked selective scan -> y
        scan_p1<<<NC*128, 256>>>(delta, xi, dbc, A_log_i, Pa, Qa);
        scan_p2<<<(NCHAN*DSTATE)/256, 256>>>(Pa, Qa, S0);
        scan_p3<<<NC*128, 256>>>(delta, xi, xz, dbc, A_log_i, D_i, S0, y);

        // dest = h + y @ out_proj_w^T    (M=4096, N=512, K=1024)
        float* dest = (i == NL - 1) ? out : h;
        gemm_tf32<128,128,32,512,false,false,true>
            <<<dim3(DMODEL/128, T/128), 512, SMB(128,128,32)>>>(
            y, ED, out_w_i, ED, nullptr, h, dest, DMODEL, ED, 0);
    }
}